// round 8
// baseline (speedup 1.0000x reference)
#include <cuda_runtime.h>
#include <cstdint>
#include <cstddef>

#define NN 1023
#define DD 1024
#define BB 4
#define TT 8192
#define SST 36   // padded smem row stride (floats): float4-aligned, conflict-free for perm layout

// k-permutation within each 32-block: thread t4's mma k-values become contiguous
#define PERM(k) (((k) & ~31) | ((((k) & 3) << 3) | (((k) >> 2) & 7)))

__device__ __align__(16) float g_states[BB * NN * DD];   // node states, D-permuted, raw proj for internal
__device__ __align__(16) float g_Wp[1024 * 2048];        // W_proj with k-permuted columns
__device__ __align__(16) float g_btp[10 * DD];           // bt with permuted d
__device__ __align__(16) float g_mixture[BB * DD];
__device__ __align__(16) float g_mixpart[8][5][DD];

// ---------------------------------------------------------------------------
// Prep: leaves mean-pool (permuted write) | zero internal nodes | permute W | permute bt
// ---------------------------------------------------------------------------
__global__ void __launch_bounds__(256) prep_kernel(const float* __restrict__ x,
                                                   const float* __restrict__ W,
                                                   const float* __restrict__ bt) {
    int blk = blockIdx.x;
    int tid = threadIdx.x;
    if (blk < 2048) {                         // leaves
        int b = blk >> 9;
        int l = blk & 511;
        const float4* xp = reinterpret_cast<const float4*>(x)
                           + ((size_t)(b * TT + l * 8)) * 256 + tid;
        float sx = 0.f, sy = 0.f, sz = 0.f, sw = 0.f;
#pragma unroll
        for (int i = 0; i < 8; i++) {
            float4 v = xp[(size_t)i * 256];
            sx += v.x; sy += v.y; sz += v.z; sw += v.w;
        }
        float* dst = g_states + ((size_t)b * NN + 511 + l) * DD;
        int d0 = tid * 4;
        dst[PERM(d0)]     = sx * 0.125f;
        dst[PERM(d0 + 1)] = sy * 0.125f;
        dst[PERM(d0 + 2)] = sz * 0.125f;
        dst[PERM(d0 + 3)] = sw * 0.125f;
    } else if (blk < 4092) {                  // zero nodes 0..510, 4 batches
        int i = (blk - 2048) * 256 + tid;
        if (i < 523264) {
            int b = i / 130816;               // 511*1024/4
            int r = i - b * 130816;
            reinterpret_cast<float4*>(g_states + (size_t)b * NN * DD)[r] =
                make_float4(0.f, 0.f, 0.f, 0.f);
        }
    } else if (blk < 6140) {                  // permute W -> g_Wp
        int idx = (blk - 4092) * 256 + tid;   // float4 index, < 524288
        float4 v = reinterpret_cast<const float4*>(W)[idx];
        int base = idx * 4;
        int n = base >> 11, k0 = base & 2047;
        float* dst = g_Wp + ((size_t)n << 11);
        dst[PERM(k0)]     = v.x;
        dst[PERM(k0 + 1)] = v.y;
        dst[PERM(k0 + 2)] = v.z;
        dst[PERM(k0 + 3)] = v.w;
    } else {                                  // permute bt -> g_btp
        int idx = (blk - 6140) * 256 + tid;
        if (idx < 2560) {
            float4 v = reinterpret_cast<const float4*>(bt)[idx];
            int base = idx * 4;
            int r = base >> 10, k0 = base & 1023;
            float* dst = g_btp + (r << 10);
            dst[PERM(k0)]     = v.x;
            dst[PERM(k0 + 1)] = v.y;
            dst[PERM(k0 + 2)] = v.z;
            dst[PERM(k0 + 3)] = v.w;
        }
    }
}

// ---------------------------------------------------------------------------
// Tree level GEMM, tf32 mma, batch folded into M, split-K atomics, cp.async
// double-buffered, permuted-k layout -> LDS.128 fragment loads, in-register
// lazy spike threshold (children level L+1). btc derived IN DEVICE CODE from
// g_btp (round-7 bug: device symbol referenced from host gave garbage ptr).
// ---------------------------------------------------------------------------
__device__ __forceinline__ void mma_tf32(float c[4], const unsigned a[4], const unsigned b[2]) {
    asm volatile(
        "mma.sync.aligned.m16n8k8.row.col.f32.tf32.tf32.f32 "
        "{%0,%1,%2,%3}, {%4,%5,%6,%7}, {%8,%9}, {%0,%1,%2,%3};\n"
        : "+f"(c[0]), "+f"(c[1]), "+f"(c[2]), "+f"(c[3])
        : "r"(a[0]), "r"(a[1]), "r"(a[2]), "r"(a[3]),
          "r"(b[0]), "r"(b[1]));
}

__device__ __forceinline__ unsigned smem_u32(const void* p) {
    return (unsigned)__cvta_generic_to_shared(p);
}

// element j (0..7) of a float4[2] register pair
#define EF(P, j) ((j) < 4 ? ((const float*)&(P)[0])[(j)] : ((const float*)&(P)[1])[(j) - 4])

__global__ void __launch_bounds__(128, 3) tree_gemm3_kernel(int level, int ls, int NL,
                                                            int Kslab) {
    // device-side pointer into the permuted bt table (level 8's A = leaves: no threshold)
    const float* btc = (level == 8) ? nullptr : (g_btp + (size_t)(level + 1) * DD);

    int split = blockIdx.z;
    int m0 = blockIdx.x * 64;
    int n0 = blockIdx.y * 64;
    int Mtot = NL * 4;
    int kbeg = split * Kslab;
    int iters = Kslab >> 5;

    __shared__ float As[2][64 * SST];
    __shared__ float Bs[2][64 * SST];
    __shared__ float tb[2][32];

    int tid = threadIdx.x;
    int warp = tid >> 5, lane = tid & 31;
    int wm = warp >> 1, wn = warp & 1;
    int g = lane >> 2, t4 = lane & 3;

    float acc[2][4][4];
#pragma unroll
    for (int i = 0; i < 2; i++)
#pragma unroll
        for (int j = 0; j < 4; j++)
#pragma unroll
            for (int k = 0; k < 4; k++) acc[i][j][k] = 0.f;

#define STAGE(buf, kg)                                                               \
    {                                                                                \
        _Pragma("unroll")                                                            \
        for (int q = 0; q < 4; q++) {                                                \
            int i = q * 128 + tid;                                                   \
            int r = i >> 3, c = i & 7;                                               \
            unsigned sa = smem_u32(&As[buf][r * SST + c * 4]);                       \
            int rg = m0 + r;                                                         \
            const float* pa = g_Wp;                                                  \
            int sz = 0;                                                              \
            if (rg < Mtot) {                                                         \
                int bb = rg >> level;                                                \
                int jj = rg & (NL - 1);                                              \
                pa = g_states + ((size_t)bb * NN + (2 * ls + 1) + 2 * jj) * DD       \
                     + (kg) + c * 4;                                                 \
                sz = 16;                                                             \
            }                                                                        \
            asm volatile("cp.async.cg.shared.global [%0], [%1], 16, %2;\n"           \
                         :: "r"(sa), "l"(pa), "r"(sz));                              \
            unsigned sb = smem_u32(&Bs[buf][r * SST + c * 4]);                       \
            const float* pb = g_Wp + (size_t)(n0 + r) * 2048 + (kg) + c * 4;         \
            asm volatile("cp.async.cg.shared.global [%0], [%1], 16;\n"               \
                         :: "r"(sb), "l"(pb));                                       \
        }                                                                            \
        if (btc && tid < 8) {                                                        \
            unsigned st = smem_u32(&tb[buf][tid * 4]);                               \
            const float* pt = btc + (((kg) & 1023) + tid * 4);                       \
            asm volatile("cp.async.ca.shared.global [%0], [%1], 16;\n"               \
                         :: "r"(st), "l"(pt));                                       \
        }                                                                            \
        asm volatile("cp.async.commit_group;\n");                                    \
    }

    STAGE(0, kbeg);

    for (int it = 0; it < iters; ++it) {
        int cur = it & 1;
        if (it + 1 < iters) {
            STAGE(cur ^ 1, kbeg + (it + 1) * 32);
            asm volatile("cp.async.wait_group 1;\n");
        } else {
            asm volatile("cp.async.wait_group 0;\n");
        }
        __syncthreads();

        // vector fragment loads: each thread's 8 k-values are contiguous (perm layout)
        float4 Ar[4][2], Br[4][2];
        int abase = (wm * 32 + g) * SST + t4 * 8;
#pragma unroll
        for (int r4 = 0; r4 < 4; r4++) {
            Ar[r4][0] = *reinterpret_cast<const float4*>(&As[cur][abase + r4 * 8 * SST]);
            Ar[r4][1] = *reinterpret_cast<const float4*>(&As[cur][abase + r4 * 8 * SST + 4]);
        }
        int bbase = (wn * 32 + g) * SST + t4 * 8;
#pragma unroll
        for (int j = 0; j < 4; j++) {
            Br[j][0] = *reinterpret_cast<const float4*>(&Bs[cur][bbase + j * 8 * SST]);
            Br[j][1] = *reinterpret_cast<const float4*>(&Bs[cur][bbase + j * 8 * SST + 4]);
        }
        if (btc) {
            float4 th0 = *reinterpret_cast<const float4*>(&tb[cur][t4 * 8]);
            float4 th1 = *reinterpret_cast<const float4*>(&tb[cur][t4 * 8 + 4]);
#pragma unroll
            for (int r4 = 0; r4 < 4; r4++) {
                Ar[r4][0].x = Ar[r4][0].x > th0.x ? Ar[r4][0].x : 0.f;
                Ar[r4][0].y = Ar[r4][0].y > th0.y ? Ar[r4][0].y : 0.f;
                Ar[r4][0].z = Ar[r4][0].z > th0.z ? Ar[r4][0].z : 0.f;
                Ar[r4][0].w = Ar[r4][0].w > th0.w ? Ar[r4][0].w : 0.f;
                Ar[r4][1].x = Ar[r4][1].x > th1.x ? Ar[r4][1].x : 0.f;
                Ar[r4][1].y = Ar[r4][1].y > th1.y ? Ar[r4][1].y : 0.f;
                Ar[r4][1].z = Ar[r4][1].z > th1.z ? Ar[r4][1].z : 0.f;
                Ar[r4][1].w = Ar[r4][1].w > th1.w ? Ar[r4][1].w : 0.f;
            }
        }
        __syncthreads();   // tile fully consumed into regs; next STAGE may overwrite

#pragma unroll
        for (int s = 0; s < 4; s++) {
            unsigned a[2][4], bf[4][2];
#pragma unroll
            for (int i = 0; i < 2; i++) {
                a[i][0] = __float_as_uint(EF(Ar[2 * i],     2 * s));
                a[i][1] = __float_as_uint(EF(Ar[2 * i + 1], 2 * s));
                a[i][2] = __float_as_uint(EF(Ar[2 * i],     2 * s + 1));
                a[i][3] = __float_as_uint(EF(Ar[2 * i + 1], 2 * s + 1));
            }
#pragma unroll
            for (int j = 0; j < 4; j++) {
                bf[j][0] = __float_as_uint(EF(Br[j], 2 * s));
                bf[j][1] = __float_as_uint(EF(Br[j], 2 * s + 1));
            }
#pragma unroll
            for (int i = 0; i < 2; i++)
#pragma unroll
                for (int j = 0; j < 4; j++)
                    mma_tf32(acc[i][j], a[i], bf[j]);
        }
    }
#undef STAGE

    // epilogue: atomic split-K accumulate of RAW proj into permuted columns
#pragma unroll
    for (int i = 0; i < 2; i++) {
        int rg = m0 + wm * 32 + i * 16 + g;
#pragma unroll
        for (int j = 0; j < 4; j++) {
            int col = n0 + wn * 32 + j * 8 + t4 * 2;
            int pc0 = PERM(col);
            int pc1 = PERM(col + 1);
            if (rg < Mtot) {
                int bb = rg >> level, jj = rg & (NL - 1);
                float* Crow = g_states + ((size_t)bb * NN + ls + jj) * DD;
                atomicAdd(&Crow[pc0], acc[i][j][0]);
                atomicAdd(&Crow[pc1], acc[i][j][1]);
            }
            int rg8 = rg + 8;
            if (rg8 < Mtot) {
                int bb = rg8 >> level, jj = rg8 & (NL - 1);
                float* Crow = g_states + ((size_t)bb * NN + ls + jj) * DD;
                atomicAdd(&Crow[pc0], acc[i][j][2]);
                atomicAdd(&Crow[pc1], acc[i][j][3]);
            }
        }
    }
}

// ---------------------------------------------------------------------------
// Mixture, two-stage; reads permuted states, true-indexed nw/bt.
// ---------------------------------------------------------------------------
__global__ void __launch_bounds__(512) mixture1_kernel(const float* __restrict__ nw,
                                                       const float* __restrict__ bt) {
    int ld = threadIdx.x & 31;
    int ln = threadIdx.x >> 5;
    int d  = blockIdx.x * 32 + ld;
    int pd = PERM(d);
    int sp = blockIdx.y;
    int nend = sp * 128 + 128;
    if (nend > NN) nend = NN;
    float Z = 0.f, a0 = 0.f, a1 = 0.f, a2 = 0.f, a3 = 0.f;
    for (int n = sp * 128 + ln; n < nend; n += 16) {
        float e = __expf(nw[n * DD + d]);
        float v0 = g_states[((size_t)0 * NN + n) * DD + pd];
        float v1 = g_states[((size_t)1 * NN + n) * DD + pd];
        float v2 = g_states[((size_t)2 * NN + n) * DD + pd];
        float v3 = g_states[((size_t)3 * NN + n) * DD + pd];
        if (n < 511) {
            int lv = 31 - __clz(n + 1);
            float thr = bt[lv * DD + d];
            v0 = v0 > thr ? v0 : 0.f;
            v1 = v1 > thr ? v1 : 0.f;
            v2 = v2 > thr ? v2 : 0.f;
            v3 = v3 > thr ? v3 : 0.f;
        }
        Z += e;
        a0 += e * v0; a1 += e * v1; a2 += e * v2; a3 += e * v3;
    }
    __shared__ float red[5][16][32];
    red[0][ln][ld] = Z;  red[1][ln][ld] = a0; red[2][ln][ld] = a1;
    red[3][ln][ld] = a2; red[4][ln][ld] = a3;
    __syncthreads();
    if (ln == 0) {
        float v[5];
#pragma unroll
        for (int k = 0; k < 5; k++) {
            float s = 0.f;
#pragma unroll
            for (int i = 0; i < 16; i++) s += red[k][i][ld];
            v[k] = s;
        }
#pragma unroll
        for (int k = 0; k < 5; k++) g_mixpart[sp][k][d] = v[k];
    }
}

__global__ void __launch_bounds__(256) mixture2_kernel() {
    int d = blockIdx.x * 256 + threadIdx.x;
    float Z = 0.f, a0 = 0.f, a1 = 0.f, a2 = 0.f, a3 = 0.f;
#pragma unroll
    for (int sp = 0; sp < 8; sp++) {
        Z  += g_mixpart[sp][0][d];
        a0 += g_mixpart[sp][1][d];
        a1 += g_mixpart[sp][2][d];
        a2 += g_mixpart[sp][3][d];
        a3 += g_mixpart[sp][4][d];
    }
    float inv = 1.f / Z;
    g_mixture[0 * DD + d] = a0 * inv;
    g_mixture[1 * DD + d] = a1 * inv;
    g_mixture[2 * DD + d] = a2 * inv;
    g_mixture[3 * DD + d] = a3 * inv;
}

// ---------------------------------------------------------------------------
// Final: out = RMSNorm(x + mixture[b]) * rms_w, 8 rows per block.
// ---------------------------------------------------------------------------
__global__ void __launch_bounds__(256) final_kernel(const float* __restrict__ x,
                                                    const float* __restrict__ rms_w,
                                                    float* __restrict__ out) {
    int blk = blockIdx.x;
    int b  = blk >> 10;
    int t0 = (blk & 1023) * 8;
    int tid = threadIdx.x;
    int lane = tid & 31, warp = tid >> 5;

    __shared__ float4 smix[256];
    __shared__ float4 srw[256];
    __shared__ float  sred[8];

    smix[tid] = reinterpret_cast<const float4*>(g_mixture + b * DD)[tid];
    srw[tid]  = reinterpret_cast<const float4*>(rms_w)[tid];
    __syncthreads();
    float4 mix = smix[tid], rw = srw[tid];

    const float4* xb = reinterpret_cast<const float4*>(x) + ((size_t)(b * TT + t0)) * 256;
    float4*       ob = reinterpret_cast<float4*>(out)     + ((size_t)(b * TT + t0)) * 256;

    for (int r = 0; r < 8; r++) {
        float4 v = xb[(size_t)r * 256 + tid];
        v.x += mix.x; v.y += mix.y; v.z += mix.z; v.w += mix.w;
        float ss = v.x * v.x + v.y * v.y + v.z * v.z + v.w * v.w;
#pragma unroll
        for (int o = 16; o > 0; o >>= 1) ss += __shfl_xor_sync(0xffffffffu, ss, o);
        __syncthreads();
        if (lane == 0) sred[warp] = ss;
        __syncthreads();
        float tot = 0.f;
#pragma unroll
        for (int i = 0; i < 8; i++) tot += sred[i];
        float inv = rsqrtf(tot * (1.0f / 1024.0f) + 1.1920929e-7f);
        float4 o4;
        o4.x = v.x * rw.x * inv; o4.y = v.y * rw.y * inv;
        o4.z = v.z * rw.z * inv; o4.w = v.w * rw.w * inv;
        ob[(size_t)r * 256 + tid] = o4;
    }
}

// ---------------------------------------------------------------------------
// launch
// ---------------------------------------------------------------------------
extern "C" void kernel_launch(void* const* d_in, const int* in_sizes, int n_in,
                              void* d_out, int out_size) {
    const float* x     = (const float*)d_in[0];
    const float* W     = (const float*)d_in[1];
    const float* nw    = (const float*)d_in[2];
    const float* bt    = (const float*)d_in[3];
    const float* rms_w = (const float*)d_in[5];   // as_w (d_in[4]) unused (×0.0)
    float* out = (float*)d_out;

    prep_kernel<<<6150, 256>>>(x, W, bt);   // leaves | zero | W-perm | bt-perm

    for (int lvl = 8; lvl >= 0; --lvl) {
        int NL = 1 << lvl;
        int ls = NL - 1;
        int Mtot = 4 * NL;
        int S = 8192 / Mtot; if (S > 16) S = 16;   // L8:8 L7..L0:16
        int Kslab = 2048 / S;
        dim3 grid((Mtot + 63) / 64, 16, S);
        tree_gemm3_kernel<<<grid, 128>>>(lvl, ls, NL, Kslab);
    }

    mixture1_kernel<<<dim3(32, 8), 512>>>(nw, bt);
    mixture2_kernel<<<4, 256>>>();
    final_kernel<<<4096, 256>>>(x, rms_w, out);
}

// round 9
// speedup vs baseline: 1.1781x; 1.1781x over previous
#include <cuda_runtime.h>
#include <cstdint>
#include <cstddef>

#define NN 1023
#define DD 1024
#define BB 4
#define TT 8192
#define SST 44   // padded smem row stride (floats): float4-aligned + conflict-free frag loads

__device__ __align__(16) float g_states[BB * NN * DD];   // node states, fp32 (raw proj for internal)
__device__ __align__(16) float g_mixture[BB * DD];
__device__ __align__(16) float g_mixpart[8][5][DD];      // [split][Z,a0..a3][d]

// ---------------------------------------------------------------------------
// Prep: blk < 2048 -> leaves mean-pool; else zero internal nodes 0..510
// (atomic split-K targets) for all batches.
// ---------------------------------------------------------------------------
__global__ void __launch_bounds__(256) prep_kernel(const float* __restrict__ x) {
    int blk = blockIdx.x;
    if (blk < 2048) {
        int b = blk >> 9;
        int l = blk & 511;
        int d4 = threadIdx.x;
        const float4* xp = reinterpret_cast<const float4*>(x)
                           + ((size_t)(b * TT + l * 8)) * 256 + d4;
        float sx = 0.f, sy = 0.f, sz = 0.f, sw = 0.f;
#pragma unroll
        for (int i = 0; i < 8; i++) {
            float4 v = xp[(size_t)i * 256];
            sx += v.x; sy += v.y; sz += v.z; sw += v.w;
        }
        float4 o;
        o.x = sx * 0.125f; o.y = sy * 0.125f; o.z = sz * 0.125f; o.w = sw * 0.125f;
        reinterpret_cast<float4*>(g_states)[((size_t)b * NN + 511 + l) * 256 + d4] = o;
    } else {
        int i = (blk - 2048) * 256 + threadIdx.x;
        if (i < 523264) {                     // 4 * 511*1024/4
            int b = i / 130816;               // 511*1024/4
            int r = i - b * 130816;
            reinterpret_cast<float4*>(g_states + (size_t)b * NN * DD)[r] =
                make_float4(0.f, 0.f, 0.f, 0.f);
        }
    }
}

// ---------------------------------------------------------------------------
// Tree level GEMM, tf32 mma, batch folded into M, split-K via atomicAdd,
// cp.async double-buffered, lazy spike threshold applied IN REGISTERS at
// A-fragment load (children level L+1 thresholds); level 8 (A = leaves)
// passes btc = null -> no threshold work.
// ---------------------------------------------------------------------------
__device__ __forceinline__ void mma_tf32(float c[4], const unsigned a[4], const unsigned b[2]) {
    asm volatile(
        "mma.sync.aligned.m16n8k8.row.col.f32.tf32.tf32.f32 "
        "{%0,%1,%2,%3}, {%4,%5,%6,%7}, {%8,%9}, {%0,%1,%2,%3};\n"
        : "+f"(c[0]), "+f"(c[1]), "+f"(c[2]), "+f"(c[3])
        : "r"(a[0]), "r"(a[1]), "r"(a[2]), "r"(a[3]),
          "r"(b[0]), "r"(b[1]));
}

__device__ __forceinline__ unsigned smem_u32(const void* p) {
    return (unsigned)__cvta_generic_to_shared(p);
}

__global__ void __launch_bounds__(128) tree_gemm2_kernel(const float* __restrict__ W,
                                                         const float* __restrict__ btc,
                                                         int level, int ls, int NL,
                                                         int Kslab) {
    int split = blockIdx.z;
    int m0 = blockIdx.x * 64;
    int n0 = blockIdx.y * 64;
    int Mtot = NL * 4;
    int kbeg = split * Kslab;
    int iters = Kslab >> 5;

    __shared__ float As[2][64 * SST];
    __shared__ float Bs[2][64 * SST];
    __shared__ float tb[2][32];          // child thresholds for this K chunk

    int tid = threadIdx.x;
    int warp = tid >> 5, lane = tid & 31;
    int wm = warp >> 1, wn = warp & 1;
    int g = lane >> 2, t4 = lane & 3;

    float acc[2][4][4];
#pragma unroll
    for (int i = 0; i < 2; i++)
#pragma unroll
        for (int j = 0; j < 4; j++)
#pragma unroll
            for (int k = 0; k < 4; k++) acc[i][j][k] = 0.f;

#define STAGE(buf, kg)                                                               \
    {                                                                                \
        _Pragma("unroll")                                                            \
        for (int q = 0; q < 4; q++) {                                                \
            int i = q * 128 + tid;                                                   \
            int r = i >> 3, c = i & 7;                                               \
            unsigned sa = smem_u32(&As[buf][r * SST + c * 4]);                       \
            int rg = m0 + r;                                                         \
            const float* pa = W;                                                     \
            int sz = 0;                                                              \
            if (rg < Mtot) {                                                         \
                int bb = rg >> level;                                                \
                int jj = rg & (NL - 1);                                              \
                pa = g_states + ((size_t)bb * NN + (2 * ls + 1) + 2 * jj) * DD       \
                     + (kg) + c * 4;                                                 \
                sz = 16;                                                             \
            }                                                                        \
            asm volatile("cp.async.cg.shared.global [%0], [%1], 16, %2;\n"           \
                         :: "r"(sa), "l"(pa), "r"(sz));                              \
            unsigned sb = smem_u32(&Bs[buf][r * SST + c * 4]);                       \
            const float* pb = W + (size_t)(n0 + r) * 2048 + (kg) + c * 4;            \
            asm volatile("cp.async.cg.shared.global [%0], [%1], 16;\n"               \
                         :: "r"(sb), "l"(pb));                                       \
        }                                                                            \
        if (btc && tid < 8) {                                                        \
            unsigned st = smem_u32(&tb[buf][tid * 4]);                               \
            const float* pt = btc + (((kg) & 1023) + tid * 4);                       \
            asm volatile("cp.async.ca.shared.global [%0], [%1], 16;\n"               \
                         :: "r"(st), "l"(pt));                                       \
        }                                                                            \
        asm volatile("cp.async.commit_group;\n");                                    \
    }

    STAGE(0, kbeg);

    for (int it = 0; it < iters; ++it) {
        int cur = it & 1;
        if (it + 1 < iters) {
            STAGE(cur ^ 1, kbeg + (it + 1) * 32);
            asm volatile("cp.async.wait_group 1;\n");
        } else {
            asm volatile("cp.async.wait_group 0;\n");
        }
        __syncthreads();

#pragma unroll
        for (int kk = 0; kk < 32; kk += 8) {
            unsigned a[2][4], bf[4][2];
            if (btc) {
                float thr_lo = tb[cur][kk + t4];
                float thr_hi = tb[cur][kk + t4 + 4];
#pragma unroll
                for (int i = 0; i < 2; i++) {
                    int rb = (wm * 32 + i * 16 + g) * SST + kk + t4;
                    float f0 = As[cur][rb];
                    float f1 = As[cur][rb + 8 * SST];
                    float f2 = As[cur][rb + 4];
                    float f3 = As[cur][rb + 8 * SST + 4];
                    a[i][0] = __float_as_uint(f0 > thr_lo ? f0 : 0.f);
                    a[i][1] = __float_as_uint(f1 > thr_lo ? f1 : 0.f);
                    a[i][2] = __float_as_uint(f2 > thr_hi ? f2 : 0.f);
                    a[i][3] = __float_as_uint(f3 > thr_hi ? f3 : 0.f);
                }
            } else {
#pragma unroll
                for (int i = 0; i < 2; i++) {
                    int rb = (wm * 32 + i * 16 + g) * SST + kk + t4;
                    a[i][0] = __float_as_uint(As[cur][rb]);
                    a[i][1] = __float_as_uint(As[cur][rb + 8 * SST]);
                    a[i][2] = __float_as_uint(As[cur][rb + 4]);
                    a[i][3] = __float_as_uint(As[cur][rb + 8 * SST + 4]);
                }
            }
#pragma unroll
            for (int j = 0; j < 4; j++) {
                int rb = (wn * 32 + j * 8 + g) * SST + kk + t4;
                bf[j][0] = __float_as_uint(Bs[cur][rb]);
                bf[j][1] = __float_as_uint(Bs[cur][rb + 4]);
            }
#pragma unroll
            for (int i = 0; i < 2; i++)
#pragma unroll
                for (int j = 0; j < 4; j++)
                    mma_tf32(acc[i][j], a[i], bf[j]);
        }
        __syncthreads();   // all reads of 'cur' done before it is restaged
    }
#undef STAGE

    // epilogue: atomic split-K accumulate of RAW proj (threshold lazy at consumers)
#pragma unroll
    for (int i = 0; i < 2; i++) {
        int rg = m0 + wm * 32 + i * 16 + g;
#pragma unroll
        for (int j = 0; j < 4; j++) {
            int col = n0 + wn * 32 + j * 8 + t4 * 2;
            if (rg < Mtot) {
                int bb = rg >> level, jj = rg & (NL - 1);
                float* Crow = g_states + ((size_t)bb * NN + ls + jj) * DD;
                atomicAdd(&Crow[col],     acc[i][j][0]);
                atomicAdd(&Crow[col + 1], acc[i][j][1]);
            }
            int rg8 = rg + 8;
            if (rg8 < Mtot) {
                int bb = rg8 >> level, jj = rg8 & (NL - 1);
                float* Crow = g_states + ((size_t)bb * NN + ls + jj) * DD;
                atomicAdd(&Crow[col],     acc[i][j][2]);
                atomicAdd(&Crow[col + 1], acc[i][j][3]);
            }
        }
    }
}

// ---------------------------------------------------------------------------
// Mixture, two-stage, lazy spike threshold per node level.
// ---------------------------------------------------------------------------
__global__ void __launch_bounds__(512) mixture1_kernel(const float* __restrict__ nw,
                                                       const float* __restrict__ bt) {
    int ld = threadIdx.x & 31;
    int ln = threadIdx.x >> 5;
    int d  = blockIdx.x * 32 + ld;
    int sp = blockIdx.y;
    int nend = sp * 128 + 128;
    if (nend > NN) nend = NN;
    float Z = 0.f, a0 = 0.f, a1 = 0.f, a2 = 0.f, a3 = 0.f;
    for (int n = sp * 128 + ln; n < nend; n += 16) {
        float e = __expf(nw[n * DD + d]);
        float v0 = g_states[((size_t)0 * NN + n) * DD + d];
        float v1 = g_states[((size_t)1 * NN + n) * DD + d];
        float v2 = g_states[((size_t)2 * NN + n) * DD + d];
        float v3 = g_states[((size_t)3 * NN + n) * DD + d];
        if (n < 511) {
            int lv = 31 - __clz(n + 1);
            float thr = bt[lv * DD + d];
            v0 = v0 > thr ? v0 : 0.f;
            v1 = v1 > thr ? v1 : 0.f;
            v2 = v2 > thr ? v2 : 0.f;
            v3 = v3 > thr ? v3 : 0.f;
        }
        Z += e;
        a0 += e * v0; a1 += e * v1; a2 += e * v2; a3 += e * v3;
    }
    __shared__ float red[5][16][32];
    red[0][ln][ld] = Z;  red[1][ln][ld] = a0; red[2][ln][ld] = a1;
    red[3][ln][ld] = a2; red[4][ln][ld] = a3;
    __syncthreads();
    if (ln == 0) {
        float v[5];
#pragma unroll
        for (int k = 0; k < 5; k++) {
            float s = 0.f;
#pragma unroll
            for (int i = 0; i < 16; i++) s += red[k][i][ld];
            v[k] = s;
        }
#pragma unroll
        for (int k = 0; k < 5; k++) g_mixpart[sp][k][d] = v[k];
    }
}

__global__ void __launch_bounds__(256) mixture2_kernel() {
    int d = blockIdx.x * 256 + threadIdx.x;
    float Z = 0.f, a0 = 0.f, a1 = 0.f, a2 = 0.f, a3 = 0.f;
#pragma unroll
    for (int sp = 0; sp < 8; sp++) {
        Z  += g_mixpart[sp][0][d];
        a0 += g_mixpart[sp][1][d];
        a1 += g_mixpart[sp][2][d];
        a2 += g_mixpart[sp][3][d];
        a3 += g_mixpart[sp][4][d];
    }
    float inv = 1.f / Z;
    g_mixture[0 * DD + d] = a0 * inv;
    g_mixture[1 * DD + d] = a1 * inv;
    g_mixture[2 * DD + d] = a2 * inv;
    g_mixture[3 * DD + d] = a3 * inv;
}

// ---------------------------------------------------------------------------
// Final: out = RMSNorm(x + mixture[b]) * rms_w, 8 rows per block.
// ---------------------------------------------------------------------------
__global__ void __launch_bounds__(256) final_kernel(const float* __restrict__ x,
                                                    const float* __restrict__ rms_w,
                                                    float* __restrict__ out) {
    int blk = blockIdx.x;
    int b  = blk >> 10;
    int t0 = (blk & 1023) * 8;
    int tid = threadIdx.x;
    int lane = tid & 31, warp = tid >> 5;

    __shared__ float4 smix[256];
    __shared__ float4 srw[256];
    __shared__ float  sred[8];

    smix[tid] = reinterpret_cast<const float4*>(g_mixture + b * DD)[tid];
    srw[tid]  = reinterpret_cast<const float4*>(rms_w)[tid];
    __syncthreads();
    float4 mix = smix[tid], rw = srw[tid];

    const float4* xb = reinterpret_cast<const float4*>(x) + ((size_t)(b * TT + t0)) * 256;
    float4*       ob = reinterpret_cast<float4*>(out)     + ((size_t)(b * TT + t0)) * 256;

    for (int r = 0; r < 8; r++) {
        float4 v = xb[(size_t)r * 256 + tid];
        v.x += mix.x; v.y += mix.y; v.z += mix.z; v.w += mix.w;
        float ss = v.x * v.x + v.y * v.y + v.z * v.z + v.w * v.w;
#pragma unroll
        for (int o = 16; o > 0; o >>= 1) ss += __shfl_xor_sync(0xffffffffu, ss, o);
        __syncthreads();
        if (lane == 0) sred[warp] = ss;
        __syncthreads();
        float tot = 0.f;
#pragma unroll
        for (int i = 0; i < 8; i++) tot += sred[i];
        float inv = rsqrtf(tot * (1.0f / 1024.0f) + 1.1920929e-7f);
        float4 o4;
        o4.x = v.x * rw.x * inv; o4.y = v.y * rw.y * inv;
        o4.z = v.z * rw.z * inv; o4.w = v.w * rw.w * inv;
        ob[(size_t)r * 256 + tid] = o4;
    }
}

// ---------------------------------------------------------------------------
// launch: prep -> L8..L0 (atomic split-K, atomic-lean S schedule) -> mixture -> final
// ---------------------------------------------------------------------------
extern "C" void kernel_launch(void* const* d_in, const int* in_sizes, int n_in,
                              void* d_out, int out_size) {
    const float* x     = (const float*)d_in[0];
    const float* W     = (const float*)d_in[1];
    const float* nw    = (const float*)d_in[2];
    const float* bt    = (const float*)d_in[3];
    const float* rms_w = (const float*)d_in[5];   // as_w (d_in[4]) unused (×0.0)
    float* out = (float*)d_out;

    prep_kernel<<<4092, 256>>>(x);    // leaves (2048) + zero nodes 0..510 (2044)

    // atomic-lean split schedule: L8:4, L7:8, L6:8, L5..L0:16
    static const int Stab[9] = {16, 16, 16, 16, 16, 16, 8, 8, 4};

    for (int lvl = 8; lvl >= 0; --lvl) {
        int NL = 1 << lvl;
        int ls = NL - 1;
        int Mtot = 4 * NL;
        int S = Stab[lvl];
        int Kslab = 2048 / S;
        dim3 grid((Mtot + 63) / 64, 16, S);
        const float* btc = (lvl == 8) ? nullptr : (bt + (size_t)(lvl + 1) * DD);
        tree_gemm2_kernel<<<grid, 128>>>(W, btc, lvl, ls, NL, Kslab);
    }

    mixture1_kernel<<<dim3(32, 8), 512>>>(nw, bt);
    mixture2_kernel<<<4, 256>>>();
    final_kernel<<<4096, 256>>>(x, rms_w, out);
}

// round 12
// speedup vs baseline: 1.2017x; 1.0200x over previous
#include <cuda_runtime.h>
#include <cstdint>
#include <cstddef>

#define NN 1023
#define DD 1024
#define BB 4
#define TT 8192
#define SST 44   // padded smem row stride (floats): float4-aligned + conflict-free frag loads

__device__ __align__(16) float g_states[BB * NN * DD];   // node states, fp32 (raw proj for internal)
__device__ __align__(16) float g_mixture[BB * DD];
__device__ __align__(16) float g_mixpart[8][5][DD];      // [split][Z,a0..a3][d]

// ---------------------------------------------------------------------------
// Prep: blk < 2048 -> leaves mean-pool; else zero internal nodes 0..510
// (split-K reduction targets) for all batches.
// ---------------------------------------------------------------------------
__global__ void __launch_bounds__(256) prep_kernel(const float* __restrict__ x) {
    int blk = blockIdx.x;
    if (blk < 2048) {
        int b = blk >> 9;
        int l = blk & 511;
        int d4 = threadIdx.x;
        const float4* xp = reinterpret_cast<const float4*>(x)
                           + ((size_t)(b * TT + l * 8)) * 256 + d4;
        float sx = 0.f, sy = 0.f, sz = 0.f, sw = 0.f;
#pragma unroll
        for (int i = 0; i < 8; i++) {
            float4 v = xp[(size_t)i * 256];
            sx += v.x; sy += v.y; sz += v.z; sw += v.w;
        }
        float4 o;
        o.x = sx * 0.125f; o.y = sy * 0.125f; o.z = sz * 0.125f; o.w = sw * 0.125f;
        reinterpret_cast<float4*>(g_states)[((size_t)b * NN + 511 + l) * 256 + d4] = o;
    } else {
        int i = (blk - 2048) * 256 + threadIdx.x;
        if (i < 523264) {                     // 4 * 511*1024/4
            int b = i / 130816;               // 511*1024/4
            int r = i - b * 130816;
            reinterpret_cast<float4*>(g_states + (size_t)b * NN * DD)[r] =
                make_float4(0.f, 0.f, 0.f, 0.f);
        }
    }
}

// ---------------------------------------------------------------------------
// Tree level GEMM, tf32 mma, batch folded into M, split-K via VECTOR red
// (red.global.add.v2.f32 -> half the LTS atomic ops), cp.async double-buffered,
// lazy spike threshold in registers at A-fragment load (children level L+1);
// level 8 (A = leaves) passes btc = null -> no threshold work.
// ---------------------------------------------------------------------------
__device__ __forceinline__ void mma_tf32(float c[4], const unsigned a[4], const unsigned b[2]) {
    asm volatile(
        "mma.sync.aligned.m16n8k8.row.col.f32.tf32.tf32.f32 "
        "{%0,%1,%2,%3}, {%4,%5,%6,%7}, {%8,%9}, {%0,%1,%2,%3};\n"
        : "+f"(c[0]), "+f"(c[1]), "+f"(c[2]), "+f"(c[3])
        : "r"(a[0]), "r"(a[1]), "r"(a[2]), "r"(a[3]),
          "r"(b[0]), "r"(b[1]));
}

__device__ __forceinline__ void red_add_v2(float* addr, float a, float b) {
    asm volatile("red.global.add.v2.f32 [%0], {%1, %2};\n"
                 :: "l"(addr), "f"(a), "f"(b) : "memory");
}

__device__ __forceinline__ unsigned smem_u32(const void* p) {
    return (unsigned)__cvta_generic_to_shared(p);
}

__global__ void __launch_bounds__(128) tree_gemm2_kernel(const float* __restrict__ W,
                                                         const float* __restrict__ btc,
                                                         int level, int ls, int NL,
                                                         int Kslab) {
    int split = blockIdx.z;
    int m0 = blockIdx.x * 64;
    int n0 = blockIdx.y * 64;
    int Mtot = NL * 4;
    int kbeg = split * Kslab;
    int iters = Kslab >> 5;

    __shared__ float As[2][64 * SST];
    __shared__ float Bs[2][64 * SST];
    __shared__ float tb[2][32];          // child thresholds for this K chunk

    int tid = threadIdx.x;
    int warp = tid >> 5, lane = tid & 31;
    int wm = warp >> 1, wn = warp & 1;
    int g = lane >> 2, t4 = lane & 3;

    float acc[2][4][4];
#pragma unroll
    for (int i = 0; i < 2; i++)
#pragma unroll
        for (int j = 0; j < 4; j++)
#pragma unroll
            for (int k = 0; k < 4; k++) acc[i][j][k] = 0.f;

#define STAGE(buf, kg)                                                               \
    {                                                                                \
        _Pragma("unroll")                                                            \
        for (int q = 0; q < 4; q++) {                                                \
            int i = q * 128 + tid;                                                   \
            int r = i >> 3, c = i & 7;                                               \
            unsigned sa = smem_u32(&As[buf][r * SST + c * 4]);                       \
            int rg = m0 + r;                                                         \
            const float* pa = W;                                                     \
            int sz = 0;                                                              \
            if (rg < Mtot) {                                                         \
                int bb = rg >> level;                                                \
                int jj = rg & (NL - 1);                                              \
                pa = g_states + ((size_t)bb * NN + (2 * ls + 1) + 2 * jj) * DD       \
                     + (kg) + c * 4;                                                 \
                sz = 16;                                                             \
            }                                                                        \
            asm volatile("cp.async.cg.shared.global [%0], [%1], 16, %2;\n"           \
                         :: "r"(sa), "l"(pa), "r"(sz));                              \
            unsigned sb = smem_u32(&Bs[buf][r * SST + c * 4]);                       \
            const float* pb = W + (size_t)(n0 + r) * 2048 + (kg) + c * 4;            \
            asm volatile("cp.async.cg.shared.global [%0], [%1], 16;\n"               \
                         :: "r"(sb), "l"(pb));                                       \
        }                                                                            \
        if (btc && tid < 8) {                                                        \
            unsigned st = smem_u32(&tb[buf][tid * 4]);                               \
            const float* pt = btc + (((kg) & 1023) + tid * 4);                       \
            asm volatile("cp.async.ca.shared.global [%0], [%1], 16;\n"               \
                         :: "r"(st), "l"(pt));                                       \
        }                                                                            \
        asm volatile("cp.async.commit_group;\n");                                    \
    }

    STAGE(0, kbeg);

    for (int it = 0; it < iters; ++it) {
        int cur = it & 1;
        if (it + 1 < iters) {
            STAGE(cur ^ 1, kbeg + (it + 1) * 32);
            asm volatile("cp.async.wait_group 1;\n");
        } else {
            asm volatile("cp.async.wait_group 0;\n");
        }
        __syncthreads();

#pragma unroll
        for (int kk = 0; kk < 32; kk += 8) {
            unsigned a[2][4], bf[4][2];
            if (btc) {
                float thr_lo = tb[cur][kk + t4];
                float thr_hi = tb[cur][kk + t4 + 4];
#pragma unroll
                for (int i = 0; i < 2; i++) {
                    int rb = (wm * 32 + i * 16 + g) * SST + kk + t4;
                    float f0 = As[cur][rb];
                    float f1 = As[cur][rb + 8 * SST];
                    float f2 = As[cur][rb + 4];
                    float f3 = As[cur][rb + 8 * SST + 4];
                    a[i][0] = __float_as_uint(f0 > thr_lo ? f0 : 0.f);
                    a[i][1] = __float_as_uint(f1 > thr_lo ? f1 : 0.f);
                    a[i][2] = __float_as_uint(f2 > thr_hi ? f2 : 0.f);
                    a[i][3] = __float_as_uint(f3 > thr_hi ? f3 : 0.f);
                }
            } else {
#pragma unroll
                for (int i = 0; i < 2; i++) {
                    int rb = (wm * 32 + i * 16 + g) * SST + kk + t4;
                    a[i][0] = __float_as_uint(As[cur][rb]);
                    a[i][1] = __float_as_uint(As[cur][rb + 8 * SST]);
                    a[i][2] = __float_as_uint(As[cur][rb + 4]);
                    a[i][3] = __float_as_uint(As[cur][rb + 8 * SST + 4]);
                }
            }
#pragma unroll
            for (int j = 0; j < 4; j++) {
                int rb = (wn * 32 + j * 8 + g) * SST + kk + t4;
                bf[j][0] = __float_as_uint(Bs[cur][rb]);
                bf[j][1] = __float_as_uint(Bs[cur][rb + 4]);
            }
#pragma unroll
            for (int i = 0; i < 2; i++)
#pragma unroll
                for (int j = 0; j < 4; j++)
                    mma_tf32(acc[i][j], a[i], bf[j]);
        }
        __syncthreads();   // all reads of 'cur' done before it is restaged
    }
#undef STAGE

    // epilogue: split-K accumulate of RAW proj via vector red (2 floats / LTS op)
#pragma unroll
    for (int i = 0; i < 2; i++) {
        int rg = m0 + wm * 32 + i * 16 + g;
#pragma unroll
        for (int j = 0; j < 4; j++) {
            int col = n0 + wn * 32 + j * 8 + t4 * 2;   // even -> 8B aligned
            if (rg < Mtot) {
                int bb = rg >> level, jj = rg & (NL - 1);
                float* Crow = g_states + ((size_t)bb * NN + ls + jj) * DD;
                red_add_v2(&Crow[col], acc[i][j][0], acc[i][j][1]);
            }
            int rg8 = rg + 8;
            if (rg8 < Mtot) {
                int bb = rg8 >> level, jj = rg8 & (NL - 1);
                float* Crow = g_states + ((size_t)bb * NN + ls + jj) * DD;
                red_add_v2(&Crow[col], acc[i][j][2], acc[i][j][3]);
            }
        }
    }
}

// ---------------------------------------------------------------------------
// Mixture, two-stage, lazy spike threshold per node level.
// ---------------------------------------------------------------------------
__global__ void __launch_bounds__(512) mixture1_kernel(const float* __restrict__ nw,
                                                       const float* __restrict__ bt) {
    int ld = threadIdx.x & 31;
    int ln = threadIdx.x >> 5;
    int d  = blockIdx.x * 32 + ld;
    int sp = blockIdx.y;
    int nend = sp * 128 + 128;
    if (nend > NN) nend = NN;
    float Z = 0.f, a0 = 0.f, a1 = 0.f, a2 = 0.f, a3 = 0.f;
    for (int n = sp * 128 + ln; n < nend; n += 16) {
        float e = __expf(nw[n * DD + d]);
        float v0 = g_states[((size_t)0 * NN + n) * DD + d];
        float v1 = g_states[((size_t)1 * NN + n) * DD + d];
        float v2 = g_states[((size_t)2 * NN + n) * DD + d];
        float v3 = g_states[((size_t)3 * NN + n) * DD + d];
        if (n < 511) {
            int lv = 31 - __clz(n + 1);
            float thr = bt[lv * DD + d];
            v0 = v0 > thr ? v0 : 0.f;
            v1 = v1 > thr ? v1 : 0.f;
            v2 = v2 > thr ? v2 : 0.f;
            v3 = v3 > thr ? v3 : 0.f;
        }
        Z += e;
        a0 += e * v0; a1 += e * v1; a2 += e * v2; a3 += e * v3;
    }
    __shared__ float red[5][16][32];
    red[0][ln][ld] = Z;  red[1][ln][ld] = a0; red[2][ln][ld] = a1;
    red[3][ln][ld] = a2; red[4][ln][ld] = a3;
    __syncthreads();
    if (ln == 0) {
        float v[5];
#pragma unroll
        for (int k = 0; k < 5; k++) {
            float s = 0.f;
#pragma unroll
            for (int i = 0; i < 16; i++) s += red[k][i][ld];
            v[k] = s;
        }
#pragma unroll
        for (int k = 0; k < 5; k++) g_mixpart[sp][k][d] = v[k];
    }
}

__global__ void __launch_bounds__(256) mixture2_kernel() {
    int d = blockIdx.x * 256 + threadIdx.x;
    float Z = 0.f, a0 = 0.f, a1 = 0.f, a2 = 0.f, a3 = 0.f;
#pragma unroll
    for (int sp = 0; sp < 8; sp++) {
        Z  += g_mixpart[sp][0][d];
        a0 += g_mixpart[sp][1][d];
        a1 += g_mixpart[sp][2][d];
        a2 += g_mixpart[sp][3][d];
        a3 += g_mixpart[sp][4][d];
    }
    float inv = 1.f / Z;
    g_mixture[0 * DD + d] = a0 * inv;
    g_mixture[1 * DD + d] = a1 * inv;
    g_mixture[2 * DD + d] = a2 * inv;
    g_mixture[3 * DD + d] = a3 * inv;
}

// ---------------------------------------------------------------------------
// Final: out = RMSNorm(x + mixture[b]) * rms_w, 8 rows per block.
// ---------------------------------------------------------------------------
__global__ void __launch_bounds__(256) final_kernel(const float* __restrict__ x,
                                                    const float* __restrict__ rms_w,
                                                    float* __restrict__ out) {
    int blk = blockIdx.x;
    int b  = blk >> 10;
    int t0 = (blk & 1023) * 8;
    int tid = threadIdx.x;
    int lane = tid & 31, warp = tid >> 5;

    __shared__ float4 smix[256];
    __shared__ float4 srw[256];
    __shared__ float  sred[8];

    smix[tid] = reinterpret_cast<const float4*>(g_mixture + b * DD)[tid];
    srw[tid]  = reinterpret_cast<const float4*>(rms_w)[tid];
    __syncthreads();
    float4 mix = smix[tid], rw = srw[tid];

    const float4* xb = reinterpret_cast<const float4*>(x) + ((size_t)(b * TT + t0)) * 256;
    float4*       ob = reinterpret_cast<float4*>(out)     + ((size_t)(b * TT + t0)) * 256;

    for (int r = 0; r < 8; r++) {
        float4 v = xb[(size_t)r * 256 + tid];
        v.x += mix.x; v.y += mix.y; v.z += mix.z; v.w += mix.w;
        float ss = v.x * v.x + v.y * v.y + v.z * v.z + v.w * v.w;
#pragma unroll
        for (int o = 16; o > 0; o >>= 1) ss += __shfl_xor_sync(0xffffffffu, ss, o);
        __syncthreads();
        if (lane == 0) sred[warp] = ss;
        __syncthreads();
        float tot = 0.f;
#pragma unroll
        for (int i = 0; i < 8; i++) tot += sred[i];
        float inv = rsqrtf(tot * (1.0f / 1024.0f) + 1.1920929e-7f);
        float4 o4;
        o4.x = v.x * rw.x * inv; o4.y = v.y * rw.y * inv;
        o4.z = v.z * rw.z * inv; o4.w = v.w * rw.w * inv;
        ob[(size_t)r * 256 + tid] = o4;
    }
}

// ---------------------------------------------------------------------------
// launch: prep -> L8..L0 (vector-red split-K, lean S schedule) -> mixture -> final
// (Round-10 kernel resubmitted unchanged; round-10 bench was an infra failure.)
// ---------------------------------------------------------------------------
extern "C" void kernel_launch(void* const* d_in, const int* in_sizes, int n_in,
                              void* d_out, int out_size) {
    const float* x     = (const float*)d_in[0];
    const float* W     = (const float*)d_in[1];
    const float* nw    = (const float*)d_in[2];
    const float* bt    = (const float*)d_in[3];
    const float* rms_w = (const float*)d_in[5];   // as_w (d_in[4]) unused (×0.0)
    float* out = (float*)d_out;

    prep_kernel<<<4092, 256>>>(x);    // leaves (2048) + zero nodes 0..510 (2044)

    // atomic-lean split schedule: index by level. L8:4 L7:4 L6:8 L5:8 L4..L0:16
    static const int Stab[9] = {16, 16, 16, 16, 16, 8, 8, 4, 4};

    for (int lvl = 8; lvl >= 0; --lvl) {
        int NL = 1 << lvl;
        int ls = NL - 1;
        int Mtot = 4 * NL;
        int S = Stab[lvl];
        int Kslab = 2048 / S;
        dim3 grid((Mtot + 63) / 64, 16, S);
        const float* btc = (lvl == 8) ? nullptr : (bt + (size_t)(lvl + 1) * DD);
        tree_gemm2_kernel<<<grid, 128>>>(W, btc, lvl, ls, NL, Kslab);
    }

    mixture1_kernel<<<dim3(32, 8), 512>>>(nw, bt);
    mixture2_kernel<<<4, 256>>>();
    final_kernel<<<4096, 256>>>(x, rms_w, out);
}